// round 6
// baseline (speedup 1.0000x reference)
#include <cuda_runtime.h>
#include <cstdint>

#define NN 50000
#define NE 800000
#define F 64
#define KF 256    // F * K
#define OUTF 256

// Scratch (device globals: allocation-free rule)
__device__ int   g_degi[NN];
__device__ int   g_rowptr[NN + 1];
__device__ int   g_cursor[NN];
__device__ int   g_csrc[NE];
__device__ __align__(16) float    g_dsqrt[NN];
__device__ __align__(16) float    g_scaled_a[NN * F];
__device__ __align__(16) float    g_scaled_b[NN * F];
__device__ __align__(16) float    g_Xt[(size_t)NN * KF];
__device__ __align__(16) uint32_t g_Xt32[(size_t)NN * KF];   // tf32 bits of g_Xt
__device__ __align__(16) uint32_t g_Wt[OUTF * KF];           // tf32, transposed [n][k]

__device__ __forceinline__ uint32_t f2tf32(float x) {
    uint32_t u;
    asm("cvt.rna.tf32.f32 %0, %1;" : "=r"(u) : "f"(x));
    return u;
}

__global__ void k_zero() {
    int i = blockIdx.x * blockDim.x + threadIdx.x;
    if (i < NN) g_degi[i] = 0;
}

__global__ void k_deg(const int* __restrict__ dst) {
    int e = blockIdx.x * blockDim.x + threadIdx.x;
    if (e < NE) atomicAdd(&g_degi[dst[e]], 1);
}

// Single-block exclusive scan over 50k degrees -> row_ptr (+ cursor copy).
__global__ __launch_bounds__(1024) void k_scan() {
    __shared__ int sums[1024];
    const int t = threadIdx.x;
    const int CH = (NN + 1023) / 1024;          // 49
    int lo = t * CH, hi = min(lo + CH, NN);
    int s = 0;
    for (int i = lo; i < hi; i++) s += g_degi[i];
    sums[t] = s;
    __syncthreads();
    for (int off = 1; off < 1024; off <<= 1) {
        int v = (t >= off) ? sums[t - off] : 0;
        __syncthreads();
        sums[t] += v;
        __syncthreads();
    }
    int base = (t == 0) ? 0 : sums[t - 1];
    for (int i = lo; i < hi; i++) {
        g_rowptr[i] = base;
        g_cursor[i] = base;
        base += g_degi[i];
    }
    if (t == 1023) g_rowptr[NN] = sums[1023];
}

__global__ void k_fill(const int* __restrict__ src, const int* __restrict__ dst) {
    int e = blockIdx.x * blockDim.x + threadIdx.x;
    if (e < NE) {
        int pos = atomicAdd(&g_cursor[dst[e]], 1);
        g_csrc[pos] = src[e];
    }
}

// W -> tf32, transposed to [n][k] for the GEMM's B-tile cp.async.
__global__ void k_wprep(const float* __restrict__ W) {
    int i = blockIdx.x * blockDim.x + threadIdx.x;   // < OUTF*KF
    int n = i >> 8, k = i & 255;
    g_Wt[(size_t)n * KF + k] = f2tf32(W[(size_t)k * OUTF + n]);
}

// One thread per (node, 4-float chunk): d^-1/2, X0 (+tf32 copy), first scaled buffer.
__global__ void k_prep(const float* __restrict__ x) {
    int t = blockIdx.x * blockDim.x + threadIdx.x;
    if (t >= NN * 16) return;
    int i = t >> 4, c = t & 15;
    float ds = rsqrtf((float)max(g_degi[i], 1));
    if (c == 0) g_dsqrt[i] = ds;
    float4 v = ((const float4*)x)[(size_t)i * 16 + c];
    ((float4*)(g_Xt + (size_t)i * KF))[c] = v;   // X0 into block 0
    uint4 tv = make_uint4(f2tf32(v.x), f2tf32(v.y), f2tf32(v.z), f2tf32(v.w));
    ((uint4*)(g_Xt32 + (size_t)i * KF))[c] = tv;
    float4 s = make_float4(v.x * ds, v.y * ds, v.z * ds, v.w * ds);
    ((float4*)g_scaled_a)[(size_t)i * 16 + c] = s;
}

// Gather-based Laplacian + fused Chebyshev recurrence. Ping-pong scaled buffers.
__global__ __launch_bounds__(256) void k_gather_cheb(const float* __restrict__ lambda_max,
                                                     int step, int ping) {
    int t = blockIdx.x * blockDim.x + threadIdx.x;
    if (t >= NN * 16) return;
    int i = t >> 4, c = t & 15;
    const float4* in = (const float4*)(ping ? g_scaled_b : g_scaled_a);
    float4* outb = (float4*)(ping ? g_scaled_a : g_scaled_b);

    int lo = g_rowptr[i], hi = g_rowptr[i + 1];
    float4 a0 = make_float4(0.f, 0.f, 0.f, 0.f);
    float4 a1 = make_float4(0.f, 0.f, 0.f, 0.f);
    float4 a2 = make_float4(0.f, 0.f, 0.f, 0.f);
    float4 a3 = make_float4(0.f, 0.f, 0.f, 0.f);
    int j = lo;
    for (; j + 3 < hi; j += 4) {
        int s0 = __ldg(&g_csrc[j]);
        int s1 = __ldg(&g_csrc[j + 1]);
        int s2 = __ldg(&g_csrc[j + 2]);
        int s3 = __ldg(&g_csrc[j + 3]);
        float4 v0 = in[(size_t)s0 * 16 + c];
        float4 v1 = in[(size_t)s1 * 16 + c];
        float4 v2 = in[(size_t)s2 * 16 + c];
        float4 v3 = in[(size_t)s3 * 16 + c];
        a0.x += v0.x; a0.y += v0.y; a0.z += v0.z; a0.w += v0.w;
        a1.x += v1.x; a1.y += v1.y; a1.z += v1.z; a1.w += v1.w;
        a2.x += v2.x; a2.y += v2.y; a2.z += v2.z; a2.w += v2.w;
        a3.x += v3.x; a3.y += v3.y; a3.z += v3.z; a3.w += v3.w;
    }
    for (; j < hi; j++) {
        int s0 = __ldg(&g_csrc[j]);
        float4 v0 = in[(size_t)s0 * 16 + c];
        a0.x += v0.x; a0.y += v0.y; a0.z += v0.z; a0.w += v0.w;
    }
    float ds = g_dsqrt[i];
    float4 L = make_float4((a0.x + a1.x + a2.x + a3.x) * ds,
                           (a0.y + a1.y + a2.y + a3.y) * ds,
                           (a0.z + a1.z + a2.z + a3.z) * ds,
                           (a0.w + a1.w + a2.w + a3.w) * ds);

    float rn = 2.0f / lambda_max[0];
    float4* XtRow = (float4*)(g_Xt + (size_t)i * KF);
    float4 xp = XtRow[(step - 1) * 16 + c];
    float4 xn;
    if (step == 1) {
        float cL = -rn, cP = rn - 1.0f;
        xn = make_float4(cL * L.x + cP * xp.x, cL * L.y + cP * xp.y,
                         cL * L.z + cP * xp.z, cL * L.w + cP * xp.w);
    } else {
        float4 xpp = XtRow[(step - 2) * 16 + c];
        float cL = -2.0f * rn, cP = 2.0f * (rn - 1.0f);
        xn = make_float4(cL * L.x + cP * xp.x - xpp.x, cL * L.y + cP * xp.y - xpp.y,
                         cL * L.z + cP * xp.z - xpp.z, cL * L.w + cP * xp.w - xpp.w);
    }
    XtRow[step * 16 + c] = xn;
    uint4 tv = make_uint4(f2tf32(xn.x), f2tf32(xn.y), f2tf32(xn.z), f2tf32(xn.w));
    ((uint4*)(g_Xt32 + (size_t)i * KF))[step * 16 + c] = tv;
    outb[(size_t)i * 16 + c] = make_float4(xn.x * ds, xn.y * ds, xn.z * ds, xn.w * ds);
}

// ---------------------------------------------------------------------------
// TF32 tensor-core GEMM with cp.async double buffering.
// out[50000,256] = relu(Xt @ W + b). 128x128 block tile, BK=16, 2 stages,
// 256 threads (8 warps, 4x2), warp tile 32x64, mma.sync.m16n8k8.tf32.
// PITCH 20: (20g + t) distinct mod 32 => conflict-free fragment LDS.
// ---------------------------------------------------------------------------
#define BK 16
#define PITCH 20

__device__ __forceinline__ void cpa16(uint32_t dst_smem, const void* src, int sz) {
    asm volatile("cp.async.cg.shared.global [%0], [%1], 16, %2;"
                 :: "r"(dst_smem), "l"(src), "r"(sz));
}

__global__ __launch_bounds__(256) void k_gemm_tc(const float* __restrict__ bias,
                                                 float* __restrict__ out) {
    __shared__ uint32_t As[2][128 * PITCH];
    __shared__ uint32_t Bs[2][128 * PITCH];

    const int tid  = threadIdx.x;
    const int lane = tid & 31;
    const int warp = tid >> 5;
    const int warp_m = warp & 3;
    const int warp_n = warp >> 2;
    const int g = lane >> 2;
    const int t = lane & 3;

    const int m0 = blockIdx.y * 128;
    const int n0 = blockIdx.x * 128;

    // cp.async mapping: each thread moves 2x16B per tile per operand.
    const int ldrow = tid >> 2;        // 0..63
    const int ldc4  = (tid & 3) * 4;   // word offset 0,4,8,12

    float c[2][8][4];
    #pragma unroll
    for (int i = 0; i < 2; i++)
        #pragma unroll
        for (int j = 0; j < 8; j++)
            #pragma unroll
            for (int r = 0; r < 4; r++) c[i][j][r] = 0.f;

    uint32_t sA = (uint32_t)__cvta_generic_to_shared(&As[0][0]);
    uint32_t sB = (uint32_t)__cvta_generic_to_shared(&Bs[0][0]);

    // ---- stage loader ----
    auto load_stage = [&](int s, int kk) {
        #pragma unroll
        for (int r = 0; r < 2; r++) {
            int row = ldrow + r * 64;
            int m = m0 + row;
            const uint32_t* srcA = g_Xt32 + (size_t)(m < NN ? m : 0) * KF + kk + ldc4;
            cpa16(sA + (s * 128 * PITCH + row * PITCH + ldc4) * 4, srcA, m < NN ? 16 : 0);
            const uint32_t* srcB = g_Wt + (size_t)(n0 + row) * KF + kk + ldc4;
            cpa16(sB + (s * 128 * PITCH + row * PITCH + ldc4) * 4, srcB, 16);
        }
    };

    load_stage(0, 0);
    asm volatile("cp.async.commit_group;");

    const int NT = KF / BK;   // 16 tiles
    for (int it = 0; it < NT; it++) {
        int s = it & 1;
        if (it + 1 < NT) load_stage(s ^ 1, (it + 1) * BK);
        asm volatile("cp.async.commit_group;");
        asm volatile("cp.async.wait_group 1;");
        __syncthreads();

        const uint32_t* A = &As[s][0];
        const uint32_t* B = &Bs[s][0];
        #pragma unroll
        for (int kt = 0; kt < 2; kt++) {
            const int k0 = kt * 8;
            uint32_t a[2][4], b[8][2];
            #pragma unroll
            for (int mt = 0; mt < 2; mt++) {
                int base = warp_m * 32 + mt * 16;
                a[mt][0] = A[(base + g) * PITCH + k0 + t];
                a[mt][1] = A[(base + g + 8) * PITCH + k0 + t];
                a[mt][2] = A[(base + g) * PITCH + k0 + t + 4];
                a[mt][3] = A[(base + g + 8) * PITCH + k0 + t + 4];
            }
            #pragma unroll
            for (int nt = 0; nt < 8; nt++) {
                int nb = warp_n * 64 + nt * 8;
                b[nt][0] = B[(nb + g) * PITCH + k0 + t];
                b[nt][1] = B[(nb + g) * PITCH + k0 + t + 4];
            }
            #pragma unroll
            for (int mt = 0; mt < 2; mt++)
                #pragma unroll
                for (int nt = 0; nt < 8; nt++) {
                    asm volatile(
                        "mma.sync.aligned.m16n8k8.row.col.f32.tf32.tf32.f32 "
                        "{%0,%1,%2,%3}, {%4,%5,%6,%7}, {%8,%9}, {%0,%1,%2,%3};"
                        : "+f"(c[mt][nt][0]), "+f"(c[mt][nt][1]),
                          "+f"(c[mt][nt][2]), "+f"(c[mt][nt][3])
                        : "r"(a[mt][0]), "r"(a[mt][1]), "r"(a[mt][2]), "r"(a[mt][3]),
                          "r"(b[nt][0]), "r"(b[nt][1]));
                }
        }
        __syncthreads();
    }

    // ---- epilogue: bias + relu ----
    #pragma unroll
    for (int nt = 0; nt < 8; nt++) {
        int col = n0 + warp_n * 64 + nt * 8 + 2 * t;
        float bx = bias[col], by = bias[col + 1];
        #pragma unroll
        for (int mt = 0; mt < 2; mt++) {
            int r0 = m0 + warp_m * 32 + mt * 16 + g;
            if (r0 < NN) {
                float2 v = make_float2(fmaxf(c[mt][nt][0] + bx, 0.f),
                                       fmaxf(c[mt][nt][1] + by, 0.f));
                *(float2*)(out + (size_t)r0 * OUTF + col) = v;
            }
            int r1 = r0 + 8;
            if (r1 < NN) {
                float2 v = make_float2(fmaxf(c[mt][nt][2] + bx, 0.f),
                                       fmaxf(c[mt][nt][3] + by, 0.f));
                *(float2*)(out + (size_t)r1 * OUTF + col) = v;
            }
        }
    }
}

extern "C" void kernel_launch(void* const* d_in, const int* in_sizes, int n_in,
                              void* d_out, int out_size) {
    const float* signal = (const float*)d_in[0];
    const int*   src    = (const int*)d_in[1];
    const int*   dst    = (const int*)d_in[2];
    const float* lam    = (const float*)d_in[3];
    const float* W      = (const float*)d_in[4];
    const float* bias   = (const float*)d_in[5];
    float* out = (float*)d_out;

    k_zero<<<(NN + 255) / 256, 256>>>();
    k_deg<<<(NE + 255) / 256, 256>>>(dst);
    k_scan<<<1, 1024>>>();
    k_fill<<<(NE + 255) / 256, 256>>>(src, dst);
    k_wprep<<<(OUTF * KF) / 256, 256>>>(W);
    k_prep<<<(NN * 16 + 255) / 256, 256>>>(signal);

    // step 1: in = a, out = b; step 2: in = b, out = a; step 3: in = a, out = b
    k_gather_cheb<<<(NN * 16 + 255) / 256, 256>>>(lam, 1, 0);
    k_gather_cheb<<<(NN * 16 + 255) / 256, 256>>>(lam, 2, 1);
    k_gather_cheb<<<(NN * 16 + 255) / 256, 256>>>(lam, 3, 0);

    k_gemm_tc<<<dim3(OUTF / 128, (NN + 127) / 128), 256>>>(bias, out);
}

// round 7
// speedup vs baseline: 1.5283x; 1.5283x over previous
#include <cuda_runtime.h>
#include <cuda_fp16.h>
#include <cstdint>

#define NN 50000
#define NE 800000
#define F 64
#define KF 256    // F * K
#define OUTF 256
#define NB 49     // scan blocks of 1024 nodes

// Scratch (device globals: allocation-free rule)
__device__ int   g_degi[NN];
__device__ int   g_rowptr[NN + 1];
__device__ int   g_cursor[NN];
__device__ int   g_csrc[NE];
__device__ int   g_psum[NB];
__device__ int   g_poff[NB];
__device__ __align__(16) float    g_dsqrt[NN];
__device__ __align__(16) uint32_t g_scaled_a[NN * F / 2];   // half2 packed
__device__ __align__(16) uint32_t g_scaled_b[NN * F / 2];
__device__ __align__(16) float    g_Xt[(size_t)NN * KF];
__device__ __align__(16) uint32_t g_Xt32[(size_t)NN * KF];  // tf32 bits of g_Xt
__device__ __align__(16) uint32_t g_Wt[OUTF * KF];          // tf32, transposed [n][k]

__device__ __forceinline__ uint32_t f2tf32(float x) {
    uint32_t u;
    asm("cvt.rna.tf32.f32 %0, %1;" : "=r"(u) : "f"(x));
    return u;
}

__global__ void k_zero() {
    int i = blockIdx.x * blockDim.x + threadIdx.x;
    if (i < NN) g_degi[i] = 0;
}

__global__ void k_deg(const int* __restrict__ dst) {
    int e = blockIdx.x * blockDim.x + threadIdx.x;
    if (e < NE) atomicAdd(&g_degi[dst[e]], 1);
}

// ---- parallel 3-stage scan --------------------------------------------------
__global__ __launch_bounds__(256) void k_scan_part() {
    __shared__ int s[256];
    int t = threadIdx.x, b = blockIdx.x;
    int base = b * 1024 + t * 4;
    int sum = 0;
    #pragma unroll
    for (int j = 0; j < 4; j++) {
        int i = base + j;
        if (i < NN) sum += g_degi[i];
    }
    s[t] = sum;
    __syncthreads();
    for (int off = 128; off > 0; off >>= 1) {
        if (t < off) s[t] += s[t + off];
        __syncthreads();
    }
    if (t == 0) g_psum[b] = s[0];
}

__global__ __launch_bounds__(64) void k_scan_top() {
    __shared__ int s[64];
    int t = threadIdx.x;
    int v = (t < NB) ? g_psum[t] : 0;
    s[t] = v;
    __syncthreads();
    for (int off = 1; off < 64; off <<= 1) {
        int u = (t >= off) ? s[t - off] : 0;
        __syncthreads();
        s[t] += u;
        __syncthreads();
    }
    if (t < NB) g_poff[t] = s[t] - v;   // exclusive
    if (t == 0) g_rowptr[NN] = NE;
}

__global__ __launch_bounds__(256) void k_scan_fill() {
    __shared__ int s[256];
    int t = threadIdx.x, b = blockIdx.x;
    int base = b * 1024 + t * 4;
    int d[4];
    int sum = 0;
    #pragma unroll
    for (int j = 0; j < 4; j++) {
        int i = base + j;
        d[j] = (i < NN) ? g_degi[i] : 0;
        sum += d[j];
    }
    s[t] = sum;
    __syncthreads();
    for (int off = 1; off < 256; off <<= 1) {
        int u = (t >= off) ? s[t - off] : 0;
        __syncthreads();
        s[t] += u;
        __syncthreads();
    }
    int off = g_poff[b] + s[t] - sum;   // exclusive within chip
    #pragma unroll
    for (int j = 0; j < 4; j++) {
        int i = base + j;
        if (i < NN) {
            g_rowptr[i] = off;
            g_cursor[i] = off;
            off += d[j];
        }
    }
}
// -----------------------------------------------------------------------------

__global__ void k_fill(const int* __restrict__ src, const int* __restrict__ dst) {
    int e = blockIdx.x * blockDim.x + threadIdx.x;
    if (e < NE) {
        int pos = atomicAdd(&g_cursor[dst[e]], 1);
        g_csrc[pos] = src[e];
    }
}

// W -> tf32, transposed to [n][k] for the GEMM's B-tile cp.async.
__global__ void k_wprep(const float* __restrict__ W) {
    int i = blockIdx.x * blockDim.x + threadIdx.x;   // < OUTF*KF
    int n = i >> 8, k = i & 255;
    g_Wt[(size_t)n * KF + k] = f2tf32(W[(size_t)k * OUTF + n]);
}

__device__ __forceinline__ uint32_t pack_h2(float a, float b) {
    __half2 h = __floats2half2_rn(a, b);
    return *(uint32_t*)&h;
}

// One thread per (node, 4-float chunk): d^-1/2, X0 (+tf32), fp16 scaled buffer.
__global__ void k_prep(const float* __restrict__ x) {
    int t = blockIdx.x * blockDim.x + threadIdx.x;
    if (t >= NN * 16) return;
    int i = t >> 4, c = t & 15;
    float ds = rsqrtf((float)max(g_degi[i], 1));
    if (c == 0) g_dsqrt[i] = ds;
    float4 v = ((const float4*)x)[(size_t)i * 16 + c];
    ((float4*)(g_Xt + (size_t)i * KF))[c] = v;   // X0 into block 0
    uint4 tv = make_uint4(f2tf32(v.x), f2tf32(v.y), f2tf32(v.z), f2tf32(v.w));
    ((uint4*)(g_Xt32 + (size_t)i * KF))[c] = tv;
    uint2 s = make_uint2(pack_h2(v.x * ds, v.y * ds), pack_h2(v.z * ds, v.w * ds));
    ((uint2*)g_scaled_a)[(size_t)i * 16 + c] = s;
}

// Gather-based Laplacian (fp16 inputs, fp32 math) + fused Chebyshev recurrence.
__global__ __launch_bounds__(256) void k_gather_cheb(const float* __restrict__ lambda_max,
                                                     int step, int ping) {
    int t = blockIdx.x * blockDim.x + threadIdx.x;
    if (t >= NN * 16) return;
    int i = t >> 4, c = t & 15;
    const uint2* in = (const uint2*)(ping ? g_scaled_b : g_scaled_a);
    uint2* outb = (uint2*)(ping ? g_scaled_a : g_scaled_b);

    int lo = g_rowptr[i], hi = g_rowptr[i + 1];
    float4 a0 = make_float4(0.f, 0.f, 0.f, 0.f);
    float4 a1 = make_float4(0.f, 0.f, 0.f, 0.f);
    float4 a2 = make_float4(0.f, 0.f, 0.f, 0.f);
    float4 a3 = make_float4(0.f, 0.f, 0.f, 0.f);

    auto acc = [&](float4& a, uint2 v) {
        float2 lo2 = __half22float2(*(__half2*)&v.x);
        float2 hi2 = __half22float2(*(__half2*)&v.y);
        a.x += lo2.x; a.y += lo2.y; a.z += hi2.x; a.w += hi2.y;
    };

    int j = lo;
    for (; j + 3 < hi; j += 4) {
        int s0 = __ldg(&g_csrc[j]);
        int s1 = __ldg(&g_csrc[j + 1]);
        int s2 = __ldg(&g_csrc[j + 2]);
        int s3 = __ldg(&g_csrc[j + 3]);
        uint2 v0 = in[(size_t)s0 * 16 + c];
        uint2 v1 = in[(size_t)s1 * 16 + c];
        uint2 v2 = in[(size_t)s2 * 16 + c];
        uint2 v3 = in[(size_t)s3 * 16 + c];
        acc(a0, v0); acc(a1, v1); acc(a2, v2); acc(a3, v3);
    }
    for (; j < hi; j++) {
        int s0 = __ldg(&g_csrc[j]);
        acc(a0, in[(size_t)s0 * 16 + c]);
    }
    float ds = g_dsqrt[i];
    float4 L = make_float4((a0.x + a1.x + a2.x + a3.x) * ds,
                           (a0.y + a1.y + a2.y + a3.y) * ds,
                           (a0.z + a1.z + a2.z + a3.z) * ds,
                           (a0.w + a1.w + a2.w + a3.w) * ds);

    float rn = 2.0f / lambda_max[0];
    float4* XtRow = (float4*)(g_Xt + (size_t)i * KF);
    float4 xp = XtRow[(step - 1) * 16 + c];
    float4 xn;
    if (step == 1) {
        float cL = -rn, cP = rn - 1.0f;
        xn = make_float4(cL * L.x + cP * xp.x, cL * L.y + cP * xp.y,
                         cL * L.z + cP * xp.z, cL * L.w + cP * xp.w);
    } else {
        float4 xpp = XtRow[(step - 2) * 16 + c];
        float cL = -2.0f * rn, cP = 2.0f * (rn - 1.0f);
        xn = make_float4(cL * L.x + cP * xp.x - xpp.x, cL * L.y + cP * xp.y - xpp.y,
                         cL * L.z + cP * xp.z - xpp.z, cL * L.w + cP * xp.w - xpp.w);
    }
    XtRow[step * 16 + c] = xn;
    uint4 tv = make_uint4(f2tf32(xn.x), f2tf32(xn.y), f2tf32(xn.z), f2tf32(xn.w));
    ((uint4*)(g_Xt32 + (size_t)i * KF))[step * 16 + c] = tv;
    uint2 s = make_uint2(pack_h2(xn.x * ds, xn.y * ds), pack_h2(xn.z * ds, xn.w * ds));
    outb[(size_t)i * 16 + c] = s;
}

// ---------------------------------------------------------------------------
// TF32 tensor-core GEMM with cp.async double buffering (unchanged from R4/R6).
// ---------------------------------------------------------------------------
#define BK 16
#define PITCH 20

__device__ __forceinline__ void cpa16(uint32_t dst_smem, const void* src, int sz) {
    asm volatile("cp.async.cg.shared.global [%0], [%1], 16, %2;"
                 :: "r"(dst_smem), "l"(src), "r"(sz));
}

__global__ __launch_bounds__(256) void k_gemm_tc(const float* __restrict__ bias,
                                                 float* __restrict__ out) {
    __shared__ uint32_t As[2][128 * PITCH];
    __shared__ uint32_t Bs[2][128 * PITCH];

    const int tid  = threadIdx.x;
    const int lane = tid & 31;
    const int warp = tid >> 5;
    const int warp_m = warp & 3;
    const int warp_n = warp >> 2;
    const int g = lane >> 2;
    const int t = lane & 3;

    const int m0 = blockIdx.y * 128;
    const int n0 = blockIdx.x * 128;

    const int ldrow = tid >> 2;        // 0..63
    const int ldc4  = (tid & 3) * 4;   // word offset 0,4,8,12

    float c[2][8][4];
    #pragma unroll
    for (int i = 0; i < 2; i++)
        #pragma unroll
        for (int j = 0; j < 8; j++)
            #pragma unroll
            for (int r = 0; r < 4; r++) c[i][j][r] = 0.f;

    uint32_t sA = (uint32_t)__cvta_generic_to_shared(&As[0][0]);
    uint32_t sB = (uint32_t)__cvta_generic_to_shared(&Bs[0][0]);

    auto load_stage = [&](int s, int kk) {
        #pragma unroll
        for (int r = 0; r < 2; r++) {
            int row = ldrow + r * 64;
            int m = m0 + row;
            const uint32_t* srcA = g_Xt32 + (size_t)(m < NN ? m : 0) * KF + kk + ldc4;
            cpa16(sA + (s * 128 * PITCH + row * PITCH + ldc4) * 4, srcA, m < NN ? 16 : 0);
            const uint32_t* srcB = g_Wt + (size_t)(n0 + row) * KF + kk + ldc4;
            cpa16(sB + (s * 128 * PITCH + row * PITCH + ldc4) * 4, srcB, 16);
        }
    };

    load_stage(0, 0);
    asm volatile("cp.async.commit_group;");

    const int NT = KF / BK;   // 16 tiles
    for (int it = 0; it < NT; it++) {
        int s = it & 1;
        if (it + 1 < NT) load_stage(s ^ 1, (it + 1) * BK);
        asm volatile("cp.async.commit_group;");
        asm volatile("cp.async.wait_group 1;");
        __syncthreads();

        const uint32_t* A = &As[s][0];
        const uint32_t* B = &Bs[s][0];
        #pragma unroll
        for (int kt = 0; kt < 2; kt++) {
            const int k0 = kt * 8;
            uint32_t a[2][4], b[8][2];
            #pragma unroll
            for (int mt = 0; mt < 2; mt++) {
                int base = warp_m * 32 + mt * 16;
                a[mt][0] = A[(base + g) * PITCH + k0 + t];
                a[mt][1] = A[(base + g + 8) * PITCH + k0 + t];
                a[mt][2] = A[(base + g) * PITCH + k0 + t + 4];
                a[mt][3] = A[(base + g + 8) * PITCH + k0 + t + 4];
            }
            #pragma unroll
            for (int nt = 0; nt < 8; nt++) {
                int nb = warp_n * 64 + nt * 8;
                b[nt][0] = B[(nb + g) * PITCH + k0 + t];
                b[nt][1] = B[(nb + g) * PITCH + k0 + t + 4];
            }
            #pragma unroll
            for (int mt = 0; mt < 2; mt++)
                #pragma unroll
                for (int nt = 0; nt < 8; nt++) {
                    asm volatile(
                        "mma.sync.aligned.m16n8k8.row.col.f32.tf32.tf32.f32 "
                        "{%0,%1,%2,%3}, {%4,%5,%6,%7}, {%8,%9}, {%0,%1,%2,%3};"
                        : "+f"(c[mt][nt][0]), "+f"(c[mt][nt][1]),
                          "+f"(c[mt][nt][2]), "+f"(c[mt][nt][3])
                        : "r"(a[mt][0]), "r"(a[mt][1]), "r"(a[mt][2]), "r"(a[mt][3]),
                          "r"(b[nt][0]), "r"(b[nt][1]));
                }
        }
        __syncthreads();
    }

    #pragma unroll
    for (int nt = 0; nt < 8; nt++) {
        int col = n0 + warp_n * 64 + nt * 8 + 2 * t;
        float bx = bias[col], by = bias[col + 1];
        #pragma unroll
        for (int mt = 0; mt < 2; mt++) {
            int r0 = m0 + warp_m * 32 + mt * 16 + g;
            if (r0 < NN) {
                float2 v = make_float2(fmaxf(c[mt][nt][0] + bx, 0.f),
                                       fmaxf(c[mt][nt][1] + by, 0.f));
                *(float2*)(out + (size_t)r0 * OUTF + col) = v;
            }
            int r1 = r0 + 8;
            if (r1 < NN) {
                float2 v = make_float2(fmaxf(c[mt][nt][2] + bx, 0.f),
                                       fmaxf(c[mt][nt][3] + by, 0.f));
                *(float2*)(out + (size_t)r1 * OUTF + col) = v;
            }
        }
    }
}

extern "C" void kernel_launch(void* const* d_in, const int* in_sizes, int n_in,
                              void* d_out, int out_size) {
    const float* signal = (const float*)d_in[0];
    const int*   src    = (const int*)d_in[1];
    const int*   dst    = (const int*)d_in[2];
    const float* lam    = (const float*)d_in[3];
    const float* W      = (const float*)d_in[4];
    const float* bias   = (const float*)d_in[5];
    float* out = (float*)d_out;

    k_zero<<<(NN + 255) / 256, 256>>>();
    k_deg<<<(NE + 255) / 256, 256>>>(dst);
    k_scan_part<<<NB, 256>>>();
    k_scan_top<<<1, 64>>>();
    k_scan_fill<<<NB, 256>>>();
    k_fill<<<(NE + 255) / 256, 256>>>(src, dst);
    k_wprep<<<(OUTF * KF) / 256, 256>>>(W);
    k_prep<<<(NN * 16 + 255) / 256, 256>>>(signal);

    // step 1: in = a, out = b; step 2: in = b, out = a; step 3: in = a, out = b
    k_gather_cheb<<<(NN * 16 + 255) / 256, 256>>>(lam, 1, 0);
    k_gather_cheb<<<(NN * 16 + 255) / 256, 256>>>(lam, 2, 1);
    k_gather_cheb<<<(NN * 16 + 255) / 256, 256>>>(lam, 3, 0);

    k_gemm_tc<<<dim3(OUTF / 128, (NN + 127) / 128), 256>>>(bias, out);
}